// round 2
// baseline (speedup 1.0000x reference)
#include <cuda_runtime.h>
#include <math.h>
#include <stdint.h>

// FCOS post-process, GB300 (sm_103a), round 2.
// zero -> single-pass score+compact (byte floor 0x3E) -> check (fallback flag)
//   -> [flag-guarded exact fallback: hist -> b1 -> compact]
//   -> refine + bitonic top-1000 + decode -> fused IoU-mask + greedy NMS + out.

#define NIMG 8
#define NCLS 80
#define HH   100
#define WW   152
#define PP   (HH*WW)          // 15200
#define CPE  (NCLS*PP)        // 1216000
#define TOPK 1000
#define KPAD 1024
#define CAP  262144
#define CAP2 2048
#define CHUNK 2048
#define NBLK ((CPE + CHUNK - 1)/CHUNK)   // 594 (fallback grid)
#define PBLK ((PP + 255)/256)            // 60  (primary grid)

// ---------------- device scratch ---------------------------------------------
__device__ unsigned long long g_cand[NIMG][CAP];     // 16 MB
__device__ unsigned int g_hist[NIMG][256];
__device__ unsigned int g_candcnt[NIMG];
__device__ unsigned int g_b1[NIMG];
__device__ unsigned int g_flag[NIMG];
__device__ float g_box [NIMG][KPAD][4];
__device__ float g_obox[NIMG][KPAD][4];
__device__ float g_area[NIMG][KPAD];
__device__ float g_lab [NIMG][KPAD];
__device__ float g_sc  [NIMG][KPAD];
__device__ unsigned int g_validbits[NIMG][32];

__device__ __forceinline__ float sigmoid_exact(float x) {
    return 1.0f / (1.0f + expf(-x));
}

// ---------------- 0: zero per-call state + output ----------------------------
__global__ void k_zero(float* out) {
    int t = blockIdx.x * blockDim.x + threadIdx.x;
    if (t < NIMG * 100 * 6) out[t] = 0.0f;
    if (t < NIMG * 256) ((unsigned int*)g_hist)[t] = 0u;
    if (t < NIMG) { g_candcnt[t] = 0u; g_flag[t] = 0u; }
}

// ---------------- 1: single-pass score + compact (primary) -------------------
// Thread owns point p for all 80 classes; centerness factor hoisted per-p.
__global__ __launch_bounds__(256) void k_score_compact(const float* __restrict__ cls,
                                                       const float* __restrict__ ctr) {
    int n = blockIdx.y;
    int p = blockIdx.x * 256 + threadIdx.x;
    if (p >= PP) return;
    float eyp = __fadd_rn(1.0f, __expf(-ctr[(size_t)n * PP + p]));
    const float* clsn = cls + (size_t)n * CPE + p;
#pragma unroll 4
    for (int c = 0; c < NCLS; c++) {
        float x = clsn[(size_t)c * PP];
        // sigmoid(x) > 0.05  <=>  x > logit(0.05); near-boundary scores < 0.06 << 0.25 floor
        if (x > -2.9444389791664403f) {
            float score = __frcp_rn(__fmul_rn(__fadd_rn(1.0f, __expf(-x)), eyp));
            unsigned sb = __float_as_uint(score);
            if (sb >= 0x3E000000u) {                         // score >= 0.25
                unsigned i = (unsigned)(p * NCLS + c);       // jax flat index p*C + c
                unsigned long long key =
                    ((unsigned long long)sb << 32) |
                    (unsigned long long)(0xFFFFFFFFu - i);   // smaller idx wins ties
                unsigned pos = atomicAdd(&g_candcnt[n], 1u);
                if (pos < CAP) g_cand[n][pos] = key;
            }
        }
    }
}

// ---------------- 2: check primary sufficiency -------------------------------
__global__ void k_check() {
    int n = threadIdx.x;
    if (n < NIMG) {
        unsigned cnt = g_candcnt[n];
        if (cnt < TOPK || cnt > CAP) { g_flag[n] = 1u; g_candcnt[n] = 0u; }
    }
}

// ---------------- 3a: fallback histogram (exact math) ------------------------
__global__ __launch_bounds__(256) void k_fb_hist(const float* __restrict__ cls,
                                                 const float* __restrict__ ctr) {
    int n = blockIdx.y;
    if (!g_flag[n]) return;
    __shared__ unsigned int sh[256];
    int t = threadIdx.x;
    sh[t] = 0u;
    __syncthreads();
    int base = blockIdx.x * CHUNK;
    const float* clsn = cls + (size_t)n * CPE;
    const float* ctrn = ctr + (size_t)n * PP;
#pragma unroll
    for (int k = 0; k < 8; k++) {
        int j = base + t + k * 256;
        if (j < CPE) {
            int p = j % PP;
            float s = sigmoid_exact(clsn[j]);
            if (s > 0.05f) {
                float score = __fmul_rn(s, sigmoid_exact(ctrn[p]));
                unsigned b = __float_as_uint(score) >> 24;
                if (b) atomicAdd(&sh[b], 1u);
            }
        }
    }
    __syncthreads();
    if (sh[t]) atomicAdd(&g_hist[n][t], sh[t]);
}

// ---------------- 3b: fallback byte threshold --------------------------------
__global__ void k_fb_b1() {
    int n = threadIdx.x;
    if (n < NIMG && g_flag[n]) {
        unsigned cum = 0, b1 = 1;
        for (int b = 255; b >= 1; b--) {
            cum += g_hist[n][b];
            if (cum >= TOPK) { b1 = (unsigned)b; break; }
        }
        g_b1[n] = b1;
    }
}

// ---------------- 3c: fallback compact (exact math) --------------------------
__global__ __launch_bounds__(256) void k_fb_compact(const float* __restrict__ cls,
                                                    const float* __restrict__ ctr) {
    int n = blockIdx.y;
    if (!g_flag[n]) return;
    int t = threadIdx.x;
    unsigned b1 = g_b1[n];
    int base = blockIdx.x * CHUNK;
    const float* clsn = cls + (size_t)n * CPE;
    const float* ctrn = ctr + (size_t)n * PP;
#pragma unroll
    for (int k = 0; k < 8; k++) {
        int j = base + t + k * 256;
        if (j < CPE) {
            int p = j % PP;
            float s = sigmoid_exact(clsn[j]);
            if (s > 0.05f) {
                float score = __fmul_rn(s, sigmoid_exact(ctrn[p]));
                unsigned sb = __float_as_uint(score);
                if ((sb >> 24) >= b1) {
                    int c = j / PP;
                    unsigned i = (unsigned)(p * NCLS + c);
                    unsigned long long key =
                        ((unsigned long long)sb << 32) |
                        (unsigned long long)(0xFFFFFFFFu - i);
                    unsigned pos = atomicAdd(&g_candcnt[n], 1u);
                    if (pos < CAP) g_cand[n][pos] = key;
                }
            }
        }
    }
}

// ---------------- 4: refine to exact s*, bitonic top-1000, decode ------------
__global__ __launch_bounds__(1024) void k_refine_sort_decode(const float* __restrict__ loc,
                                                             const float* __restrict__ reg,
                                                             const float* __restrict__ info) {
    __shared__ unsigned long long slist[CAP2];
    __shared__ unsigned int shist[256];
    __shared__ unsigned int s_pfx, s_r, s_cnt2;
    int n = blockIdx.x;
    int t = threadIdx.x;
    unsigned M = g_candcnt[n];
    if (M > CAP) M = CAP;
    if (t == 0) { s_pfx = 0u; s_r = TOPK; s_cnt2 = 0u; }
    __syncthreads();
    for (int lvl = 3; lvl >= 0; lvl--) {
        if (t < 256) shist[t] = 0u;
        __syncthreads();
        unsigned pfx = s_pfx;
        for (unsigned idx = t; idx < M; idx += 1024) {
            unsigned bits = (unsigned)(g_cand[n][idx] >> 32);
            bool cond = (lvl == 3) || ((bits >> ((lvl + 1) * 8)) == pfx);
            if (cond) atomicAdd(&shist[(bits >> (lvl * 8)) & 255u], 1u);
        }
        __syncthreads();
        if (t == 0) {
            unsigned cum = 0, rr = s_r; int chosen = 0;
            for (int b = 255; b >= 0; b--) {
                cum += shist[b];
                if (cum >= rr) { chosen = b; s_r = rr - (cum - shist[b]); break; }
            }
            s_pfx = (s_pfx << 8) | (unsigned)chosen;
        }
        __syncthreads();
    }
    unsigned sstar = s_pfx;
    for (int q = t; q < CAP2; q += 1024) slist[q] = 0ull;
    __syncthreads();
    for (unsigned idx = t; idx < M; idx += 1024) {
        unsigned long long key = g_cand[n][idx];
        if ((unsigned)(key >> 32) >= sstar) {
            unsigned pos = atomicAdd(&s_cnt2, 1u);
            if (pos < CAP2) slist[pos] = key;
        }
    }
    __syncthreads();
    for (int k2 = 2; k2 <= CAP2; k2 <<= 1) {
        for (int s = k2 >> 1; s >= 1; s >>= 1) {
            int i = ((t & ~(s - 1)) << 1) | (t & (s - 1));
            int l = i | s;
            unsigned long long a = slist[i], b = slist[l];
            bool dir = ((i & k2) == 0);
            if ((a < b) == dir) { slist[i] = b; slist[l] = a; }
            __syncthreads();
        }
    }
    // ---- inline decode (t = rank) ----
    float x1 = 0, y1 = 0, x2 = 0, y2 = 0, labf = 0, score = 0;
    float ox1 = 0, oy1 = 0, ox2 = 0, oy2 = 0, area = 0;
    bool valid = false;
    if (t < TOPK) {
        unsigned long long key = slist[t];
        unsigned sb = (unsigned)(key >> 32);
        if (sb) {
            score = __uint_as_float(sb);
            unsigned i = 0xFFFFFFFFu - (unsigned)(key & 0xFFFFFFFFull);
            int p = (int)(i / NCLS);
            int c = (int)(i - (unsigned)(p * NCLS));
            labf = (float)(c + 1);
            float lx = loc[2 * p], ly = loc[2 * p + 1];
            float rl = reg[((size_t)(n * 4 + 0)) * PP + p];
            float rt = reg[((size_t)(n * 4 + 1)) * PP + p];
            float rr = reg[((size_t)(n * 4 + 2)) * PP + p];
            float rb = reg[((size_t)(n * 4 + 3)) * PP + p];
            float hm1 = __fsub_rn(info[2 * n + 0], 1.0f);
            float wm1 = __fsub_rn(info[2 * n + 1], 1.0f);
            x1 = fminf(fmaxf(__fsub_rn(lx, rl), 0.0f), wm1);
            y1 = fminf(fmaxf(__fsub_rn(ly, rt), 0.0f), hm1);
            x2 = fminf(fmaxf(__fadd_rn(lx, rr), 0.0f), wm1);
            y2 = fminf(fmaxf(__fadd_rn(ly, rb), 0.0f), hm1);
            valid = (score > 0.0f) &&
                    (__fsub_rn(x2, x1) >= 0.0f) && (__fsub_rn(y2, y1) >= 0.0f);
            float off = __fmul_rn(labf, 1.0e5f);
            ox1 = __fadd_rn(x1, off); oy1 = __fadd_rn(y1, off);
            ox2 = __fadd_rn(x2, off); oy2 = __fadd_rn(y2, off);
            area = __fmul_rn(fmaxf(__fsub_rn(ox2, ox1), 0.0f),
                             fmaxf(__fsub_rn(oy2, oy1), 0.0f));
        }
    }
    g_box[n][t][0] = x1; g_box[n][t][1] = y1; g_box[n][t][2] = x2; g_box[n][t][3] = y2;
    g_obox[n][t][0] = ox1; g_obox[n][t][1] = oy1; g_obox[n][t][2] = ox2; g_obox[n][t][3] = oy2;
    g_area[n][t] = area; g_lab[n][t] = labf; g_sc[n][t] = score;
    unsigned bal = __ballot_sync(0xffffffffu, valid);
    if ((t & 31) == 0) g_validbits[n][t >> 5] = bal;
}

// ---------------- 5: fused IoU mask (smem) + greedy NMS + output -------------
// dynamic smem: mask[1024][32] (128KB) | obox float4[1024] | area[1024] | lab[1024]
#define SM_MASK_BYTES (KPAD * 32 * 4)
#define SM_OB_BYTES   (KPAD * 16)
#define SM_AR_BYTES   (KPAD * 4)
#define SM_LB_BYTES   (KPAD * 4)
#define SM_TOTAL_BYTES (SM_MASK_BYTES + SM_OB_BYTES + SM_AR_BYTES + SM_LB_BYTES)

__global__ __launch_bounds__(256, 1) void k_mask_nms(float* __restrict__ out) {
    extern __shared__ unsigned char dyn[];
    unsigned* smask = (unsigned*)dyn;
    float4*   sob   = (float4*)(dyn + SM_MASK_BYTES);
    float*    sar   = (float*)(dyn + SM_MASK_BYTES + SM_OB_BYTES);
    float*    slb   = (float*)(dyn + SM_MASK_BYTES + SM_OB_BYTES + SM_AR_BYTES);
    int n = blockIdx.x;
    int t = threadIdx.x;
    for (int q = t; q < KPAD; q += 256) {
        sob[q] = *(const float4*)&g_obox[n][q][0];
        sar[q] = g_area[n][q];
        slb[q] = g_lab[n][q];
    }
    __syncthreads();
    // mask: warp handles row i (uniform), lane = word w
    for (int it = 0; it < 128; it++) {
        int q = t + 256 * it;          // 0..32767
        int i = q >> 5, w = q & 31;
        unsigned bits = 0u;
        if (w >= (i >> 5)) {
            float4 bi = sob[i];
            float ai = sar[i];
            float li = slb[i];
            int jb = w * 32;
#pragma unroll
            for (int b = 0; b < 32; b++) {
                int j = jb + b;
                if (j > i && slb[j] == li) {     // cross-class offset -> IoU exactly 0
                    float4 bj = sob[j];
                    float wv = fmaxf(__fsub_rn(fminf(bi.z, bj.z), fmaxf(bi.x, bj.x)), 0.0f);
                    float hv = fmaxf(__fsub_rn(fminf(bi.w, bj.w), fmaxf(bi.y, bj.y)), 0.0f);
                    float inter = __fmul_rn(wv, hv);
                    float denom = __fadd_rn(__fsub_rn(__fadd_rn(ai, sar[j]), inter), 1e-9f);
                    // iou > 0.6  <=>  inter > 0.6*denom (denom > 0)
                    if (inter > __fmul_rn(0.6f, denom)) bits |= (1u << b);
                }
            }
        }
        smask[i * 32 + w] = bits;
    }
    __syncthreads();
    // serial greedy NMS on warp 0, all-LDS
    if (t < 32) {
        int lane = t;
        unsigned validw = g_validbits[n][lane];
        unsigned removew = 0u;
        for (int g = 0; g < 32; g++) {
            unsigned cur_sup = __shfl_sync(0xffffffffu, removew, g);
            unsigned cur_val = __shfl_sync(0xffffffffu, validw, g);
            unsigned rowv[32], diag[32];
#pragma unroll
            for (int b = 0; b < 32; b++) {
                rowv[b] = smask[(g * 32 + b) * 32 + lane];
                diag[b] = smask[(g * 32 + b) * 32 + g];
            }
#pragma unroll
            for (int b = 0; b < 32; b++) {
                bool alive = ((cur_val >> b) & 1u) && !((cur_sup >> b) & 1u);
                if (alive) { removew |= rowv[b]; cur_sup |= diag[b]; }
            }
        }
        unsigned keepw = validw & ~removew;
        int cnt = __popc(keepw);
        int inc = cnt;
        for (int o = 1; o < 32; o <<= 1) {
            int v = __shfl_up_sync(0xffffffffu, inc, o);
            if (lane >= o) inc += v;
        }
        int basei = inc - cnt;
        unsigned m = keepw;
        while (m) {
            int b = __ffs(m) - 1;
            m &= m - 1;
            int rank = basei + __popc(keepw & ((1u << b) - 1u));
            if (rank < 100) {
                int i = lane * 32 + b;
                float* o6 = out + ((size_t)n * 100 + rank) * 6;
                o6[0] = g_box[n][i][0]; o6[1] = g_box[n][i][1];
                o6[2] = g_box[n][i][2]; o6[3] = g_box[n][i][3];
                o6[4] = g_lab[n][i];    o6[5] = g_sc[n][i];
            }
        }
    }
}

// ---------------- launch -----------------------------------------------------
extern "C" void kernel_launch(void* const* d_in, const int* in_sizes, int n_in,
                              void* d_out, int out_size) {
    const float* loc  = (const float*)d_in[0];
    const float* cls  = (const float*)d_in[1];
    const float* reg  = (const float*)d_in[2];
    const float* ctr  = (const float*)d_in[3];
    const float* info = (const float*)d_in[4];
    float* out = (float*)d_out;
    (void)in_sizes; (void)n_in; (void)out_size;

    cudaFuncSetAttribute(k_mask_nms, cudaFuncAttributeMaxDynamicSharedMemorySize,
                         SM_TOTAL_BYTES);

    k_zero<<<5, 1024>>>(out);
    dim3 gp(PBLK, NIMG);
    k_score_compact<<<gp, 256>>>(cls, ctr);
    k_check<<<1, 32>>>();
    dim3 gf(NBLK, NIMG);
    k_fb_hist<<<gf, 256>>>(cls, ctr);
    k_fb_b1<<<1, 32>>>();
    k_fb_compact<<<gf, 256>>>(cls, ctr);
    k_refine_sort_decode<<<NIMG, 1024>>>(loc, reg, info);
    k_mask_nms<<<NIMG, 256, SM_TOTAL_BYTES>>>(out);
}

// round 3
// speedup vs baseline: 4.2527x; 4.2527x over previous
#include <cuda_runtime.h>
#include <math.h>
#include <stdint.h>

// FCOS post-process, GB300 (sm_103a), round 3.
// sampled 14-bit threshold -> single exact-compact scan (verified) -> refine ->
// mask -> NMS. Exact fallback chain guarded by runtime completeness check.

#define NIMG 8
#define NCLS 80
#define PP   15200
#define CPE  (NCLS*PP)        // 1216000
#define TOPK 1000
#define KPAD 1024
#define CAP  262144
#define CAP2 2048
#define NSAMP 950             // PP/16 sampled points per image
#define TARGET_S 160          // sampled cum target (~2.5x margin over 1000/16)
#define C0 (-2.9444389791664403f)   // logit(0.05)

// ---------------- device scratch ---------------------------------------------
__device__ unsigned long long g_cand[NIMG][CAP];     // 16 MB
__device__ unsigned int g_hist14[NIMG][16384];
__device__ unsigned int g_hist8[NIMG][256];
__device__ unsigned int g_candcnt[NIMG];
__device__ unsigned int g_T[NIMG];
__device__ unsigned int g_gate[NIMG];
__device__ unsigned int g_b1[NIMG];
__device__ unsigned int g_flag[NIMG];
__device__ float g_box [NIMG][KPAD][4];
__device__ float g_obox[NIMG][KPAD][4];
__device__ float g_area[NIMG][KPAD];
__device__ float g_lab [NIMG][KPAD];
__device__ float g_sc  [NIMG][KPAD];
__device__ unsigned int g_validbits[NIMG][32];
__device__ unsigned int g_mask[NIMG][KPAD][32];      // 1 MB

__device__ __forceinline__ float sig_exact(float v) {
    return 1.0f / (1.0f + expf(-v));
}
// approx score: MUST be the identical op sequence in sample & compact kernels
__device__ __forceinline__ float score_apx(float x, float eyp) {
    return __frcp_rn(__fmul_rn(__fadd_rn(1.0f, __expf(-x)), eyp));
}

// ---------------- 0: zero state + output -------------------------------------
__global__ void k_zero(float* out) {
    int t = blockIdx.x * blockDim.x + threadIdx.x;   // 131072 threads
    ((unsigned int*)g_hist14)[t] = 0u;
    if (t < NIMG * 100 * 6) out[t] = 0.0f;
    if (t < NIMG * 256) ((unsigned int*)g_hist8)[t] = 0u;
    if (t < NIMG) { g_candcnt[t] = 0u; g_flag[t] = 0u; }
}

// ---------------- 1: sampled 14-bit histogram (stride-16 points) -------------
__global__ __launch_bounds__(256) void k_sample(const float* __restrict__ cls,
                                                const float* __restrict__ ctr) {
    int n = blockIdx.y;
    int k = blockIdx.x * 256 + threadIdx.x;
    if (k >= NSAMP) return;
    int p = k * 16;
    float eyp = __fadd_rn(1.0f, __expf(-ctr[(size_t)n * PP + p]));
    const float* clsn = cls + (size_t)n * CPE + p;
#pragma unroll 4
    for (int c = 0; c < NCLS; c++) {
        float x = clsn[(size_t)c * PP];
        if (x > C0) {
            unsigned b14 = __float_as_uint(score_apx(x, eyp)) >> 18;
            if (b14) atomicAdd(&g_hist14[n][b14], 1u);
        }
    }
}

// ---------------- 2: pick 14-bit threshold T, gate = T-1 ---------------------
__global__ void k_t14() {
    int n = threadIdx.x;
    if (n < NIMG) {
        unsigned cum = 0, T = 1;
        for (int b = 4095; b >= 1; b--) {         // scores < 1.0 -> b14 <= 4063
            cum += g_hist14[n][b];
            if (cum >= TARGET_S) { T = (unsigned)b; break; }
        }
        g_T[n] = T;
        g_gate[n] = (T > 2) ? (T - 1) : 1u;
    }
}

// ---------------- 3: single full scan: exact compact, gated ------------------
// grid (15, 4, NIMG): thread owns 4 consecutive points (float4), 20 classes.
__global__ __launch_bounds__(256) void k_compact(const float* __restrict__ cls,
                                                 const float* __restrict__ ctr) {
    int n = blockIdx.z;
    unsigned gate = g_gate[n];
    int q = blockIdx.x * 256 + threadIdx.x;       // float4-point index
    bool active = (q < PP / 4);
    int pb = active ? q * 4 : 0;
    float4 y4 = *(const float4*)(ctr + (size_t)n * PP + pb);
    float ey[4];
    ey[0] = __fadd_rn(1.0f, __expf(-y4.x));
    ey[1] = __fadd_rn(1.0f, __expf(-y4.y));
    ey[2] = __fadd_rn(1.0f, __expf(-y4.z));
    ey[3] = __fadd_rn(1.0f, __expf(-y4.w));
    float yv[4] = {y4.x, y4.y, y4.z, y4.w};
    int c0 = blockIdx.y * 20;
    const float* base = cls + (size_t)n * CPE + pb;
    for (int cc = 0; cc < 20; cc++) {
        int c = c0 + cc;
        float4 xv = *(const float4*)(base + (size_t)c * PP);
        float xs[4] = {xv.x, xv.y, xv.z, xv.w};
#pragma unroll
        for (int j = 0; j < 4; j++) {
            float x = xs[j];
            bool keep = false;
            unsigned long long key = 0ull;
            if (active && x > C0) {
                unsigned b14 = __float_as_uint(score_apx(x, ey[j])) >> 18;
                if (b14 >= gate) {
                    float s = sig_exact(x);                 // exact path (rare)
                    if (s > 0.05f) {
                        float sc = sig_exact(yv[j]);
                        float score = __fmul_rn(s, sc);
                        unsigned sb = __float_as_uint(score);
                        unsigned idx = (unsigned)((pb + j) * NCLS + c);
                        key = ((unsigned long long)sb << 32) |
                              (unsigned long long)(0xFFFFFFFFu - idx);
                        keep = true;
                    }
                }
            }
            unsigned bal = __ballot_sync(0xffffffffu, keep);
            if (bal) {
                int leader = __ffs(bal) - 1;
                int lane = threadIdx.x & 31;
                unsigned basep = 0;
                if (lane == leader)
                    basep = atomicAdd(&g_candcnt[n], (unsigned)__popc(bal));
                basep = __shfl_sync(0xffffffffu, basep, leader);
                if (keep) {
                    unsigned pos = basep + __popc(bal & ((1u << lane) - 1u));
                    if (pos < CAP) g_cand[n][pos] = key;
                }
            }
        }
    }
}

// ---------------- fallback A: exact 8-bit histogram (flag-guarded) -----------
__global__ __launch_bounds__(256) void k_fbA(const float* __restrict__ cls,
                                             const float* __restrict__ ctr) {
    int n = blockIdx.y;
    if (!g_flag[n]) return;
    __shared__ unsigned int sh[256];
    int t = threadIdx.x;
    sh[t] = 0u;
    __syncthreads();
    int b0 = blockIdx.x * 16384;
    const float* clsn = cls + (size_t)n * CPE;
    const float* ctrn = ctr + (size_t)n * PP;
    for (int k = 0; k < 64; k++) {
        int j = b0 + t + k * 256;
        if (j < CPE) {
            int p = j % PP;
            float s = sig_exact(clsn[j]);
            if (s > 0.05f) {
                unsigned b = __float_as_uint(__fmul_rn(s, sig_exact(ctrn[p]))) >> 24;
                if (b) atomicAdd(&sh[b], 1u);
            }
        }
    }
    __syncthreads();
    if (sh[t]) atomicAdd(&g_hist8[n][t], sh[t]);
}

__global__ void k_fbB() {
    int n = threadIdx.x;
    if (n < NIMG && g_flag[n]) {
        unsigned cum = 0, b1 = 1;
        for (int b = 255; b >= 1; b--) {
            cum += g_hist8[n][b];
            if (cum >= TOPK) { b1 = (unsigned)b; break; }
        }
        g_b1[n] = b1;
        g_candcnt[n] = 0u;
    }
}

__global__ __launch_bounds__(256) void k_fbC(const float* __restrict__ cls,
                                             const float* __restrict__ ctr) {
    int n = blockIdx.y;
    if (!g_flag[n]) return;
    int t = threadIdx.x;
    unsigned b1 = g_b1[n];
    int b0 = blockIdx.x * 16384;
    const float* clsn = cls + (size_t)n * CPE;
    const float* ctrn = ctr + (size_t)n * PP;
    for (int k = 0; k < 64; k++) {
        int j = b0 + t + k * 256;
        if (j < CPE) {
            int p = j % PP;
            float s = sig_exact(clsn[j]);
            if (s > 0.05f) {
                float score = __fmul_rn(s, sig_exact(ctrn[p]));
                unsigned sb = __float_as_uint(score);
                if ((sb >> 24) >= b1) {
                    int c = j / PP;
                    unsigned i = (unsigned)(p * NCLS + c);
                    unsigned long long key = ((unsigned long long)sb << 32) |
                                             (unsigned long long)(0xFFFFFFFFu - i);
                    unsigned pos = atomicAdd(&g_candcnt[n], 1u);
                    if (pos < CAP) g_cand[n][pos] = key;
                }
            }
        }
    }
}

// ---------------- refine: exact s*, bitonic top-1000, decode -----------------
// mode 0: primary (with completeness check); mode 1: fallback redo (flagged only)
__global__ __launch_bounds__(1024) void k_refine(int mode,
                                                 const float* __restrict__ loc,
                                                 const float* __restrict__ reg,
                                                 const float* __restrict__ info) {
    __shared__ unsigned long long slist[CAP2];
    __shared__ unsigned int shist[256];
    __shared__ unsigned int s_pfx, s_r, s_cnt2, s_chk;
    int n = blockIdx.x;
    int t = threadIdx.x;
    if (mode == 1 && !g_flag[n]) return;
    unsigned attempted = g_candcnt[n];
    unsigned M = attempted > CAP ? CAP : attempted;
    if (mode == 0) {
        if (t == 0) s_chk = 0u;
        __syncthreads();
        unsigned Vb = g_T[n] << 18;                // exact-score bits lower edge
        unsigned local = 0;
        for (unsigned idx = t; idx < M; idx += 1024)
            if ((unsigned)(g_cand[n][idx] >> 32) >= Vb) local++;
        if (local) atomicAdd(&s_chk, local);
        __syncthreads();
        if (s_chk < TOPK || attempted > CAP) {     // not provably complete
            if (t == 0) g_flag[n] = 1u;
            return;
        }
    }
    if (t == 0) { s_pfx = 0u; s_r = TOPK; s_cnt2 = 0u; }
    __syncthreads();
    for (int lvl = 3; lvl >= 0; lvl--) {
        if (t < 256) shist[t] = 0u;
        __syncthreads();
        unsigned pfx = s_pfx;
        for (unsigned idx = t; idx < M; idx += 1024) {
            unsigned bits = (unsigned)(g_cand[n][idx] >> 32);
            bool cond = (lvl == 3) || ((bits >> ((lvl + 1) * 8)) == pfx);
            if (cond) atomicAdd(&shist[(bits >> (lvl * 8)) & 255u], 1u);
        }
        __syncthreads();
        if (t == 0) {
            unsigned cum = 0, rr = s_r; int chosen = 0;
            for (int b = 255; b >= 0; b--) {
                cum += shist[b];
                if (cum >= rr) { chosen = b; s_r = rr - (cum - shist[b]); break; }
            }
            s_pfx = (s_pfx << 8) | (unsigned)chosen;
        }
        __syncthreads();
    }
    unsigned sstar = s_pfx;
    for (int q2 = t; q2 < CAP2; q2 += 1024) slist[q2] = 0ull;
    __syncthreads();
    for (unsigned idx = t; idx < M; idx += 1024) {
        unsigned long long key = g_cand[n][idx];
        if ((unsigned)(key >> 32) >= sstar) {
            unsigned pos = atomicAdd(&s_cnt2, 1u);
            if (pos < CAP2) slist[pos] = key;
        }
    }
    __syncthreads();
    for (int k2 = 2; k2 <= CAP2; k2 <<= 1) {
        for (int s2 = k2 >> 1; s2 >= 1; s2 >>= 1) {
            int i = ((t & ~(s2 - 1)) << 1) | (t & (s2 - 1));
            int l = i | s2;
            unsigned long long a = slist[i], b = slist[l];
            bool dir = ((i & k2) == 0);
            if ((a < b) == dir) { slist[i] = b; slist[l] = a; }
            __syncthreads();
        }
    }
    // decode (t = rank)
    float x1 = 0, y1 = 0, x2 = 0, y2 = 0, labf = 0, score = 0;
    float ox1 = 0, oy1 = 0, ox2 = 0, oy2 = 0, area = 0;
    bool valid = false;
    if (t < TOPK) {
        unsigned long long key = slist[t];
        unsigned sb = (unsigned)(key >> 32);
        if (sb) {
            score = __uint_as_float(sb);
            unsigned i = 0xFFFFFFFFu - (unsigned)(key & 0xFFFFFFFFull);
            int p = (int)(i / NCLS);
            int c = (int)(i - (unsigned)(p * NCLS));
            labf = (float)(c + 1);
            float lx = loc[2 * p], ly = loc[2 * p + 1];
            float rl = reg[((size_t)(n * 4 + 0)) * PP + p];
            float rt = reg[((size_t)(n * 4 + 1)) * PP + p];
            float rr = reg[((size_t)(n * 4 + 2)) * PP + p];
            float rb = reg[((size_t)(n * 4 + 3)) * PP + p];
            float hm1 = __fsub_rn(info[2 * n + 0], 1.0f);
            float wm1 = __fsub_rn(info[2 * n + 1], 1.0f);
            x1 = fminf(fmaxf(__fsub_rn(lx, rl), 0.0f), wm1);
            y1 = fminf(fmaxf(__fsub_rn(ly, rt), 0.0f), hm1);
            x2 = fminf(fmaxf(__fadd_rn(lx, rr), 0.0f), wm1);
            y2 = fminf(fmaxf(__fadd_rn(ly, rb), 0.0f), hm1);
            valid = (score > 0.0f) &&
                    (__fsub_rn(x2, x1) >= 0.0f) && (__fsub_rn(y2, y1) >= 0.0f);
            float off = __fmul_rn(labf, 1.0e5f);
            ox1 = __fadd_rn(x1, off); oy1 = __fadd_rn(y1, off);
            ox2 = __fadd_rn(x2, off); oy2 = __fadd_rn(y2, off);
            area = __fmul_rn(fmaxf(__fsub_rn(ox2, ox1), 0.0f),
                             fmaxf(__fsub_rn(oy2, oy1), 0.0f));
        }
    }
    g_box[n][t][0] = x1; g_box[n][t][1] = y1; g_box[n][t][2] = x2; g_box[n][t][3] = y2;
    g_obox[n][t][0] = ox1; g_obox[n][t][1] = oy1; g_obox[n][t][2] = ox2; g_obox[n][t][3] = oy2;
    g_area[n][t] = area; g_lab[n][t] = labf; g_sc[n][t] = score;
    unsigned bal = __ballot_sync(0xffffffffu, valid);
    if ((t & 31) == 0) g_validbits[n][t >> 5] = bal;
}

// ---------------- mask: suppression bits, 8 blocks/image ---------------------
__global__ __launch_bounds__(256) void k_mask() {
    __shared__ float4 sob[KPAD];
    __shared__ float  sar[KPAD];
    __shared__ float  slb[KPAD];
    int n = blockIdx.y;
    int t = threadIdx.x;
    for (int q = t; q < KPAD; q += 256) {
        sob[q] = *(const float4*)&g_obox[n][q][0];
        sar[q] = g_area[n][q];
        slb[q] = g_lab[n][q];
    }
    __syncthreads();
    int warp = t >> 5, lane = t & 31;
    for (int rr = 0; rr < 16; rr++) {
        int i = blockIdx.x * 128 + warp * 16 + rr;
        float4 bi = sob[i];
        float ai = sar[i];
        float li = slb[i];
        int w0 = i >> 5;
        unsigned myword = 0u;
        for (int w = w0; w < 32; w++) {          // w uniform across warp
            int j = w * 32 + lane;               // lanes consecutive: no conflicts
            bool lm = (j > i) && (slb[j] == li);
            bool sup = false;
            if (__ballot_sync(0xffffffffu, lm)) {
                if (lm) {
                    float4 bj = sob[j];
                    float wv = fmaxf(__fsub_rn(fminf(bi.z, bj.z), fmaxf(bi.x, bj.x)), 0.0f);
                    float hv = fmaxf(__fsub_rn(fminf(bi.w, bj.w), fmaxf(bi.y, bj.y)), 0.0f);
                    float inter = __fmul_rn(wv, hv);
                    float denom = __fadd_rn(__fsub_rn(__fadd_rn(ai, sar[j]), inter), 1e-9f);
                    sup = inter > __fmul_rn(0.6f, denom);   // iou > 0.6
                }
            }
            unsigned bits = __ballot_sync(0xffffffffu, sup);
            if (lane == w) myword = bits;
        }
        g_mask[n][i][lane] = (lane >= w0) ? myword : 0u;
    }
}

// ---------------- NMS: serial greedy on smem mask + output -------------------
__global__ __launch_bounds__(256, 1) void k_nms(float* __restrict__ out) {
    extern __shared__ unsigned int smask[];      // 1024 x 32 words = 128KB
    int n = blockIdx.x;
    int t = threadIdx.x;
    const uint4* src = (const uint4*)&g_mask[n][0][0];
    uint4* dst = (uint4*)smask;
    for (int q = t; q < KPAD * 8; q += 256) dst[q] = src[q];
    __syncthreads();
    if (t < 32) {
        int lane = t;
        unsigned validw = g_validbits[n][lane];
        unsigned removew = 0u;
        for (int g = 0; g < 32; g++) {
            unsigned cur_sup = __shfl_sync(0xffffffffu, removew, g);
            unsigned cur_val = __shfl_sync(0xffffffffu, validw, g);
            unsigned rowv[32], diag[32];
#pragma unroll
            for (int b = 0; b < 32; b++) {
                rowv[b] = smask[(g * 32 + b) * 32 + lane];
                diag[b] = smask[(g * 32 + b) * 32 + g];
            }
#pragma unroll
            for (int b = 0; b < 32; b++) {
                bool alive = ((cur_val >> b) & 1u) && !((cur_sup >> b) & 1u);
                if (alive) { removew |= rowv[b]; cur_sup |= diag[b]; }
            }
        }
        unsigned keepw = validw & ~removew;
        int cnt = __popc(keepw);
        int inc = cnt;
        for (int o = 1; o < 32; o <<= 1) {
            int v = __shfl_up_sync(0xffffffffu, inc, o);
            if (lane >= o) inc += v;
        }
        int basei = inc - cnt;
        unsigned m = keepw;
        while (m) {
            int b = __ffs(m) - 1;
            m &= m - 1;
            int rank = basei + __popc(keepw & ((1u << b) - 1u));
            if (rank < 100) {
                int i = lane * 32 + b;
                float* o6 = out + ((size_t)n * 100 + rank) * 6;
                o6[0] = g_box[n][i][0]; o6[1] = g_box[n][i][1];
                o6[2] = g_box[n][i][2]; o6[3] = g_box[n][i][3];
                o6[4] = g_lab[n][i];    o6[5] = g_sc[n][i];
            }
        }
    }
}

// ---------------- launch -----------------------------------------------------
extern "C" void kernel_launch(void* const* d_in, const int* in_sizes, int n_in,
                              void* d_out, int out_size) {
    const float* loc  = (const float*)d_in[0];
    const float* cls  = (const float*)d_in[1];
    const float* reg  = (const float*)d_in[2];
    const float* ctr  = (const float*)d_in[3];
    const float* info = (const float*)d_in[4];
    float* out = (float*)d_out;
    (void)in_sizes; (void)n_in; (void)out_size;

    cudaFuncSetAttribute(k_nms, cudaFuncAttributeMaxDynamicSharedMemorySize,
                         KPAD * 32 * 4);

    k_zero<<<256, 512>>>(out);
    k_sample<<<dim3(4, NIMG), 256>>>(cls, ctr);
    k_t14<<<1, 32>>>();
    k_compact<<<dim3(15, 4, NIMG), 256>>>(cls, ctr);
    k_refine<<<NIMG, 1024>>>(0, loc, reg, info);
    k_fbA<<<dim3(75, NIMG), 256>>>(cls, ctr);
    k_fbB<<<1, 32>>>();
    k_fbC<<<dim3(75, NIMG), 256>>>(cls, ctr);
    k_refine<<<NIMG, 1024>>>(1, loc, reg, info);
    k_mask<<<dim3(8, NIMG), 256>>>();
    k_nms<<<NIMG, 256, KPAD * 32 * 4>>>(out);
}

// round 4
// speedup vs baseline: 4.6582x; 1.0954x over previous
#include <cuda_runtime.h>
#include <math.h>
#include <stdint.h>

// FCOS post-process, GB300 (sm_103a), round 4.
// sampled 14-bit threshold -> per-point algebraic xmin prefilter ->
// compare-only full scan w/ exact rescoring of rare passers (verified) ->
// direct sort (<=2048) or radix refine -> mask -> NMS. Exact fallback guarded.

#define NIMG 8
#define NCLS 80
#define PP   15200
#define CPE  (NCLS*PP)        // 1216000
#define TOPK 1000
#define KPAD 1024
#define CAP  262144
#define CAP2 2048
#define NSAMP 950             // PP/16 sampled points per image
#define TARGET_S 100          // sampled cum target (~1.6x margin over 1000/16)
#define C0 (-2.9444389791664403f)   // logit(0.05)
typedef unsigned long long ull;

// ---------------- device scratch ---------------------------------------------
__device__ ull g_cand[NIMG][CAP];                    // 16 MB
__device__ unsigned int g_hist14[NIMG][4096];
__device__ unsigned int g_hist8[NIMG][256];
__device__ unsigned int g_candcnt[NIMG];
__device__ unsigned int g_T[NIMG];
__device__ float g_edgef[NIMG];
__device__ unsigned int g_b1[NIMG];
__device__ unsigned int g_flag[NIMG];
__device__ float g_xmin[NIMG][PP];
__device__ float g_box [NIMG][KPAD][4];
__device__ float g_obox[NIMG][KPAD][4];
__device__ float g_area[NIMG][KPAD];
__device__ float g_lab [NIMG][KPAD];
__device__ float g_sc  [NIMG][KPAD];
__device__ unsigned int g_validbits[NIMG][32];
__device__ unsigned int g_mask[NIMG][KPAD][32];      // 1 MB

__device__ __forceinline__ float sig_exact(float v) {
    return 1.0f / (1.0f + expf(-v));
}
__device__ __forceinline__ float score_apx(float x, float eyp) {
    return __frcp_rn(__fmul_rn(__fadd_rn(1.0f, __expf(-x)), eyp));
}

// ---------------- 0: zero state + output -------------------------------------
__global__ void k_zero(float* out) {
    int t = blockIdx.x * blockDim.x + threadIdx.x;   // 40960 threads
    if (t < NIMG * 4096) ((unsigned int*)g_hist14)[t] = 0u;
    if (t < NIMG * 100 * 6) out[t] = 0.0f;
    if (t < NIMG * 256) ((unsigned int*)g_hist8)[t] = 0u;
    if (t < NIMG) { g_candcnt[t] = 0u; g_flag[t] = 0u; }
}

// ---------------- 1: sampled 14-bit histogram --------------------------------
// item = (sample k, class-block cb of 8); batched loads for MLP.
__global__ __launch_bounds__(256) void k_sample(const float* __restrict__ cls,
                                                const float* __restrict__ ctr) {
    int n = blockIdx.y;
    int item = blockIdx.x * 256 + threadIdx.x;
    if (item >= NSAMP * 10) return;
    int k = item % NSAMP;
    int cb = item / NSAMP;
    int p = k * 16;
    float eyp = __fadd_rn(1.0f, __expf(-ctr[(size_t)n * PP + p]));
    const float* base = cls + (size_t)n * CPE + p + (size_t)cb * 8 * PP;
    float xs[8];
#pragma unroll
    for (int i = 0; i < 8; i++) xs[i] = base[(size_t)i * PP];
#pragma unroll
    for (int i = 0; i < 8; i++) {
        if (xs[i] > C0) {
            unsigned b14 = __float_as_uint(score_apx(xs[i], eyp)) >> 18;
            if (b14 > 4095u) b14 = 4095u;
            if (b14) atomicAdd(&g_hist14[n][b14], 1u);
        }
    }
}

// ---------------- 2: parallel threshold pick (block per image) ---------------
__global__ __launch_bounds__(256) void k_t14() {
    __shared__ unsigned int ss[256];
    int n = blockIdx.x;
    int t = threadIdx.x;
    unsigned loc[16]; unsigned s = 0;
#pragma unroll
    for (int i = 0; i < 16; i++) { loc[i] = g_hist14[n][t * 16 + i]; s += loc[i]; }
    ss[t] = s;
    __syncthreads();
    for (int off = 1; off < 256; off <<= 1) {        // suffix scan
        unsigned v = (t + off < 256) ? ss[t + off] : 0u;
        __syncthreads();
        ss[t] += v;
        __syncthreads();
    }
    unsigned mine = ss[t];
    unsigned above = (t + 1 < 256) ? ss[t + 1] : 0u;
    if (mine >= TARGET_S && above < TARGET_S) {      // unique crossing chunk
        unsigned cum = above, T = 1;
        for (int i = 15; i >= 0; i--) {
            cum += loc[i];
            if (cum >= TARGET_S) { T = (unsigned)(t * 16 + i); break; }
        }
        if (T < 1) T = 1;
        unsigned gate = (T > 2) ? T - 1 : 1u;
        g_T[n] = T;
        g_edgef[n] = __uint_as_float(gate << 18);
    }
    if (t == 0 && ss[0] < TARGET_S) {                // degenerate: keep all
        g_T[n] = 1;
        g_edgef[n] = __uint_as_float(1u << 18);
    }
}

// ---------------- 3: per-point xmin ------------------------------------------
// score >= edge  =>  e^-x <= 1/(edge*(1+e^-y)) - 1  =>  x >= xmin (w/ margin)
__global__ __launch_bounds__(256) void k_xmin(const float* __restrict__ ctr) {
    int n = blockIdx.y;
    int p = blockIdx.x * 256 + threadIdx.x;
    if (p >= PP) return;
    float edge = g_edgef[n];
    float eyp = __fadd_rn(1.0f, __expf(-ctr[(size_t)n * PP + p]));
    float K = __fdividef(1.0f, __fmul_rn(edge, eyp)) - 1.0f;
    g_xmin[n][p] = (K > 0.0f) ? (-__logf(K) - 0.002f) : 3.0e38f;
}

// ---------------- 4: full scan: compare-gated, exact rescoring ---------------
// grid (15, 10, NIMG): thread owns 4 points (float4) x 8 classes.
__global__ __launch_bounds__(256) void k_compact(const float* __restrict__ cls,
                                                 const float* __restrict__ ctr) {
    int n = blockIdx.z;
    int q = blockIdx.x * 256 + threadIdx.x;
    if (q >= PP / 4) return;
    int pb = q * 4;
    float4 xm4 = *(const float4*)&g_xmin[n][pb];
    float xm[4] = {xm4.x, xm4.y, xm4.z, xm4.w};
    int c0 = blockIdx.y * 8;
    const float* base = cls + (size_t)n * CPE + pb;
    const float* ctrn = ctr + (size_t)n * PP;
    float4 xv[8];
#pragma unroll
    for (int cc = 0; cc < 8; cc++)
        xv[cc] = *(const float4*)(base + (size_t)(c0 + cc) * PP);
#pragma unroll
    for (int cc = 0; cc < 8; cc++) {
        float xs[4] = {xv[cc].x, xv[cc].y, xv[cc].z, xv[cc].w};
#pragma unroll
        for (int j = 0; j < 4; j++) {
            float x = xs[j];
            if (x > C0 && x >= xm[j]) {              // rare (~2K/image)
                float s = sig_exact(x);
                if (s > 0.05f) {
                    float score = __fmul_rn(s, sig_exact(ctrn[pb + j]));
                    unsigned sb = __float_as_uint(score);
                    unsigned idx = (unsigned)((pb + j) * NCLS + (c0 + cc));
                    ull key = ((ull)sb << 32) | (ull)(0xFFFFFFFFu - idx);
                    unsigned pos = atomicAdd(&g_candcnt[n], 1u);
                    if (pos < CAP) g_cand[n][pos] = key;
                }
            }
        }
    }
}

// ---------------- fallback: exact full chain (flag-guarded) ------------------
__global__ __launch_bounds__(256) void k_fbA(const float* __restrict__ cls,
                                             const float* __restrict__ ctr) {
    int n = blockIdx.y;
    if (!g_flag[n]) return;
    __shared__ unsigned int sh[256];
    int t = threadIdx.x;
    sh[t] = 0u;
    __syncthreads();
    int b0 = blockIdx.x * 16384;
    const float* clsn = cls + (size_t)n * CPE;
    const float* ctrn = ctr + (size_t)n * PP;
    for (int k = 0; k < 64; k++) {
        int j = b0 + t + k * 256;
        if (j < CPE) {
            int p = j % PP;
            float s = sig_exact(clsn[j]);
            if (s > 0.05f) {
                unsigned b = __float_as_uint(__fmul_rn(s, sig_exact(ctrn[p]))) >> 24;
                if (b) atomicAdd(&sh[b], 1u);
            }
        }
    }
    __syncthreads();
    if (sh[t]) atomicAdd(&g_hist8[n][t], sh[t]);
}

__global__ void k_fbB() {
    int n = threadIdx.x;
    if (n < NIMG && g_flag[n]) {
        unsigned cum = 0, b1 = 1;
        for (int b = 255; b >= 1; b--) {
            cum += g_hist8[n][b];
            if (cum >= TOPK) { b1 = (unsigned)b; break; }
        }
        g_b1[n] = b1;
        g_candcnt[n] = 0u;
    }
}

__global__ __launch_bounds__(256) void k_fbC(const float* __restrict__ cls,
                                             const float* __restrict__ ctr) {
    int n = blockIdx.y;
    if (!g_flag[n]) return;
    int t = threadIdx.x;
    unsigned b1 = g_b1[n];
    int b0 = blockIdx.x * 16384;
    const float* clsn = cls + (size_t)n * CPE;
    const float* ctrn = ctr + (size_t)n * PP;
    for (int k = 0; k < 64; k++) {
        int j = b0 + t + k * 256;
        if (j < CPE) {
            int p = j % PP;
            float s = sig_exact(clsn[j]);
            if (s > 0.05f) {
                float score = __fmul_rn(s, sig_exact(ctrn[p]));
                unsigned sb = __float_as_uint(score);
                if ((sb >> 24) >= b1) {
                    int c = j / PP;
                    unsigned i = (unsigned)(p * NCLS + c);
                    ull key = ((ull)sb << 32) | (ull)(0xFFFFFFFFu - i);
                    unsigned pos = atomicAdd(&g_candcnt[n], 1u);
                    if (pos < CAP) g_cand[n][pos] = key;
                }
            }
        }
    }
}

// ---------------- refine: verify, (direct | radix), bitonic, decode ----------
__global__ __launch_bounds__(1024) void k_refine(int mode,
                                                 const float* __restrict__ loc,
                                                 const float* __restrict__ reg,
                                                 const float* __restrict__ info) {
    __shared__ ull slist[CAP2];
    __shared__ unsigned int shist[256];
    __shared__ unsigned int s_pfx, s_r, s_cnt2, s_chk;
    int n = blockIdx.x;
    int t = threadIdx.x;
    if (mode == 1 && !g_flag[n]) return;
    unsigned attempted = g_candcnt[n];
    unsigned M = attempted > CAP ? CAP : attempted;
    if (mode == 0) {
        if (t == 0) s_chk = 0u;
        __syncthreads();
        unsigned Vb = g_T[n] << 18;
        unsigned local = 0;
        for (unsigned idx = t; idx < M; idx += 1024)
            if ((unsigned)(g_cand[n][idx] >> 32) >= Vb) local++;
        if (local) atomicAdd(&s_chk, local);
        __syncthreads();
        if (s_chk < TOPK || attempted > CAP) {       // not provably complete
            if (t == 0) g_flag[n] = 1u;
            return;
        }
    }
    if (M <= CAP2) {
        // direct: sort all stored keys
        for (int q = t; q < CAP2; q += 1024)
            slist[q] = (q < (int)M) ? g_cand[n][q] : 0ull;
        __syncthreads();
    } else {
        // radix refine to exact 1000th-score threshold, then compact
        if (t == 0) { s_pfx = 0u; s_r = TOPK; s_cnt2 = 0u; }
        __syncthreads();
        for (int lvl = 3; lvl >= 0; lvl--) {
            if (t < 256) shist[t] = 0u;
            __syncthreads();
            unsigned pfx = s_pfx;
            for (unsigned idx = t; idx < M; idx += 1024) {
                unsigned bits = (unsigned)(g_cand[n][idx] >> 32);
                bool cond = (lvl == 3) || ((bits >> ((lvl + 1) * 8)) == pfx);
                if (cond) atomicAdd(&shist[(bits >> (lvl * 8)) & 255u], 1u);
            }
            __syncthreads();
            if (t == 0) {
                unsigned cum = 0, rr = s_r; int chosen = 0;
                for (int b = 255; b >= 0; b--) {
                    cum += shist[b];
                    if (cum >= rr) { chosen = b; s_r = rr - (cum - shist[b]); break; }
                }
                s_pfx = (s_pfx << 8) | (unsigned)chosen;
            }
            __syncthreads();
        }
        unsigned sstar = s_pfx;
        for (int q = t; q < CAP2; q += 1024) slist[q] = 0ull;
        __syncthreads();
        for (unsigned idx = t; idx < M; idx += 1024) {
            ull key = g_cand[n][idx];
            if ((unsigned)(key >> 32) >= sstar) {
                unsigned pos = atomicAdd(&s_cnt2, 1u);
                if (pos < CAP2) slist[pos] = key;
            }
        }
        __syncthreads();
    }
    // bitonic sort descending
    for (int k2 = 2; k2 <= CAP2; k2 <<= 1) {
        for (int s2 = k2 >> 1; s2 >= 1; s2 >>= 1) {
            int i = ((t & ~(s2 - 1)) << 1) | (t & (s2 - 1));
            int l = i | s2;
            ull a = slist[i], b = slist[l];
            bool dir = ((i & k2) == 0);
            if ((a < b) == dir) { slist[i] = b; slist[l] = a; }
            __syncthreads();
        }
    }
    // decode (t = rank)
    float x1 = 0, y1 = 0, x2 = 0, y2 = 0, labf = 0, score = 0;
    float ox1 = 0, oy1 = 0, ox2 = 0, oy2 = 0, area = 0;
    bool valid = false;
    if (t < TOPK) {
        ull key = slist[t];
        unsigned sb = (unsigned)(key >> 32);
        if (sb) {
            score = __uint_as_float(sb);
            unsigned i = 0xFFFFFFFFu - (unsigned)(key & 0xFFFFFFFFull);
            int p = (int)(i / NCLS);
            int c = (int)(i - (unsigned)(p * NCLS));
            labf = (float)(c + 1);
            float lx = loc[2 * p], ly = loc[2 * p + 1];
            float rl = reg[((size_t)(n * 4 + 0)) * PP + p];
            float rt = reg[((size_t)(n * 4 + 1)) * PP + p];
            float rr = reg[((size_t)(n * 4 + 2)) * PP + p];
            float rb = reg[((size_t)(n * 4 + 3)) * PP + p];
            float hm1 = __fsub_rn(info[2 * n + 0], 1.0f);
            float wm1 = __fsub_rn(info[2 * n + 1], 1.0f);
            x1 = fminf(fmaxf(__fsub_rn(lx, rl), 0.0f), wm1);
            y1 = fminf(fmaxf(__fsub_rn(ly, rt), 0.0f), hm1);
            x2 = fminf(fmaxf(__fadd_rn(lx, rr), 0.0f), wm1);
            y2 = fminf(fmaxf(__fadd_rn(ly, rb), 0.0f), hm1);
            valid = (score > 0.0f) &&
                    (__fsub_rn(x2, x1) >= 0.0f) && (__fsub_rn(y2, y1) >= 0.0f);
            float off = __fmul_rn(labf, 1.0e5f);
            ox1 = __fadd_rn(x1, off); oy1 = __fadd_rn(y1, off);
            ox2 = __fadd_rn(x2, off); oy2 = __fadd_rn(y2, off);
            area = __fmul_rn(fmaxf(__fsub_rn(ox2, ox1), 0.0f),
                             fmaxf(__fsub_rn(oy2, oy1), 0.0f));
        }
    }
    g_box[n][t][0] = x1; g_box[n][t][1] = y1; g_box[n][t][2] = x2; g_box[n][t][3] = y2;
    g_obox[n][t][0] = ox1; g_obox[n][t][1] = oy1; g_obox[n][t][2] = ox2; g_obox[n][t][3] = oy2;
    g_area[n][t] = area; g_lab[n][t] = labf; g_sc[n][t] = score;
    unsigned bal = __ballot_sync(0xffffffffu, valid);
    if ((t & 31) == 0) g_validbits[n][t >> 5] = bal;
}

// ---------------- mask: suppression bits, 8 blocks/image ---------------------
__global__ __launch_bounds__(256) void k_mask() {
    __shared__ float4 sob[KPAD];
    __shared__ float  sar[KPAD];
    __shared__ float  slb[KPAD];
    int n = blockIdx.y;
    int t = threadIdx.x;
    for (int q = t; q < KPAD; q += 256) {
        sob[q] = *(const float4*)&g_obox[n][q][0];
        sar[q] = g_area[n][q];
        slb[q] = g_lab[n][q];
    }
    __syncthreads();
    int warp = t >> 5, lane = t & 31;
    for (int rr = 0; rr < 16; rr++) {
        int i = blockIdx.x * 128 + warp * 16 + rr;
        float4 bi = sob[i];
        float ai = sar[i];
        float li = slb[i];
        int w0 = i >> 5;
        unsigned myword = 0u;
        for (int w = w0; w < 32; w++) {
            int j = w * 32 + lane;
            bool lm = (j > i) && (slb[j] == li);
            bool sup = false;
            if (__ballot_sync(0xffffffffu, lm)) {
                if (lm) {
                    float4 bj = sob[j];
                    float wv = fmaxf(__fsub_rn(fminf(bi.z, bj.z), fmaxf(bi.x, bj.x)), 0.0f);
                    float hv = fmaxf(__fsub_rn(fminf(bi.w, bj.w), fmaxf(bi.y, bj.y)), 0.0f);
                    float inter = __fmul_rn(wv, hv);
                    float denom = __fadd_rn(__fsub_rn(__fadd_rn(ai, sar[j]), inter), 1e-9f);
                    sup = inter > __fmul_rn(0.6f, denom);
                }
            }
            unsigned bits = __ballot_sync(0xffffffffu, sup);
            if (lane == w) myword = bits;
        }
        g_mask[n][i][lane] = (lane >= w0) ? myword : 0u;
    }
}

// ---------------- NMS: serial greedy on smem mask + output -------------------
__global__ __launch_bounds__(256, 1) void k_nms(float* __restrict__ out) {
    extern __shared__ unsigned int smask[];
    int n = blockIdx.x;
    int t = threadIdx.x;
    const uint4* src = (const uint4*)&g_mask[n][0][0];
    uint4* dst = (uint4*)smask;
    for (int q = t; q < KPAD * 8; q += 256) dst[q] = src[q];
    __syncthreads();
    if (t < 32) {
        int lane = t;
        unsigned validw = g_validbits[n][lane];
        unsigned removew = 0u;
        for (int g = 0; g < 32; g++) {
            unsigned cur_sup = __shfl_sync(0xffffffffu, removew, g);
            unsigned cur_val = __shfl_sync(0xffffffffu, validw, g);
            unsigned rowv[32], diag[32];
#pragma unroll
            for (int b = 0; b < 32; b++) {
                rowv[b] = smask[(g * 32 + b) * 32 + lane];
                diag[b] = smask[(g * 32 + b) * 32 + g];
            }
#pragma unroll
            for (int b = 0; b < 32; b++) {
                bool alive = ((cur_val >> b) & 1u) && !((cur_sup >> b) & 1u);
                if (alive) { removew |= rowv[b]; cur_sup |= diag[b]; }
            }
        }
        unsigned keepw = validw & ~removew;
        int cnt = __popc(keepw);
        int inc = cnt;
        for (int o = 1; o < 32; o <<= 1) {
            int v = __shfl_up_sync(0xffffffffu, inc, o);
            if (lane >= o) inc += v;
        }
        int basei = inc - cnt;
        unsigned m = keepw;
        while (m) {
            int b = __ffs(m) - 1;
            m &= m - 1;
            int rank = basei + __popc(keepw & ((1u << b) - 1u));
            if (rank < 100) {
                int i = lane * 32 + b;
                float* o6 = out + ((size_t)n * 100 + rank) * 6;
                o6[0] = g_box[n][i][0]; o6[1] = g_box[n][i][1];
                o6[2] = g_box[n][i][2]; o6[3] = g_box[n][i][3];
                o6[4] = g_lab[n][i];    o6[5] = g_sc[n][i];
            }
        }
    }
}

// ---------------- launch -----------------------------------------------------
extern "C" void kernel_launch(void* const* d_in, const int* in_sizes, int n_in,
                              void* d_out, int out_size) {
    const float* loc  = (const float*)d_in[0];
    const float* cls  = (const float*)d_in[1];
    const float* reg  = (const float*)d_in[2];
    const float* ctr  = (const float*)d_in[3];
    const float* info = (const float*)d_in[4];
    float* out = (float*)d_out;
    (void)in_sizes; (void)n_in; (void)out_size;

    cudaFuncSetAttribute(k_nms, cudaFuncAttributeMaxDynamicSharedMemorySize,
                         KPAD * 32 * 4);

    k_zero<<<40, 1024>>>(out);
    k_sample<<<dim3(38, NIMG), 256>>>(cls, ctr);
    k_t14<<<NIMG, 256>>>();
    k_xmin<<<dim3(60, NIMG), 256>>>(ctr);
    k_compact<<<dim3(15, 10, NIMG), 256>>>(cls, ctr);
    k_refine<<<NIMG, 1024>>>(0, loc, reg, info);
    k_fbA<<<dim3(75, NIMG), 256>>>(cls, ctr);
    k_fbB<<<1, 32>>>();
    k_fbC<<<dim3(75, NIMG), 256>>>(cls, ctr);
    k_refine<<<NIMG, 1024>>>(1, loc, reg, info);
    k_mask<<<dim3(8, NIMG), 256>>>();
    k_nms<<<NIMG, 256, KPAD * 32 * 4>>>(out);
}